// round 8
// baseline (speedup 1.0000x reference)
#include <cuda_runtime.h>
#include <cuda_bf16.h>

// Problem constants (fixed shapes for this problem instance)
#define NMAX 100000
#define EMAX 6400000
#define HID  256
#define OUT  64
#define NT   32      // nodes per MLP tile
#define SCAN_BLKS ((NMAX + 1023) / 1024)   // 98

// Scratch (device globals: no allocation allowed in kernel_launch)
__device__ float g_xl[NMAX * 4];    // stride 4, 16B rows
__device__ float g_h1[NMAX * 16];   // stride 16, 64B rows
__device__ float g_h2[NMAX * 28];   // stride 28
__device__ int    g_count[NMAX];
__device__ int    g_off[NMAX + 1];
__device__ int    g_rank[EMAX];            // per-edge rank within its dst bucket
__device__ int    g_part[SCAN_BLKS];       // per-block sums
__device__ int    g_part_off[SCAN_BLKS];   // exclusive offsets of block sums
__device__ int    g_arrive_ctr;            // grid-sync arrive counter (reset each use)
__device__ int    g_release_ctr;           // grid-sync release epoch (monotone)
__device__ float4 g_edges[EMAX];    // {src(as int bits), k0, k1, k2} sorted by dst

// packed f32x2 helpers (bit-identical to scalar fp32 math)
#define FMA_F32X2(acc, a, b) \
    asm("fma.rn.f32x2 %0, %1, %2, %0;" : "+l"(acc) : "l"(a), "l"(b))
#define PACK_DUP(out, s) \
    asm("mov.b64 %0, {%1, %1};" : "=l"(out) : "f"(s))
#define PACK2(out, lo, hi) \
    asm("mov.b64 %0, {%1, %2};" : "=l"(out) : "f"(lo), "f"(hi))
#define UNPACK2(lo, hi, in) \
    asm("mov.b64 {%0, %1}, %2;" : "=f"(lo), "=f"(hi) : "l"(in))

// ---------------------------------------------------------------------------
// xl + zero fused: xl[n,i] = sum_j gauges[n,j,i]*x[n,j]; g_count[n] = 0
// ---------------------------------------------------------------------------
__global__ void xl_zero_kernel(const float* __restrict__ x,
                               const float* __restrict__ g, int N) {
    int n = blockIdx.x * blockDim.x + threadIdx.x;
    if (n >= N) return;
    g_count[n] = 0;
    float x0 = x[n * 3 + 0], x1 = x[n * 3 + 1], x2 = x[n * 3 + 2];
    const float* G = g + n * 9;
    float o0 = x0 * G[0] + x1 * G[3] + x2 * G[6];
    float o1 = x0 * G[1] + x1 * G[4] + x2 * G[7];
    float o2 = x0 * G[2] + x1 * G[5] + x2 * G[8];
    ((float4*)g_xl)[n] = make_float4(o0, o1, o2, 0.f);
}

// ---------------------------------------------------------------------------
// Histogram + rank: the atomicAdd return value IS the edge's rank within its
// dst bucket. Stored coalesced; place_kernel then needs no atomics at all.
// ---------------------------------------------------------------------------
__global__ void hist_kernel(const int* __restrict__ ei, int E) {
    int i = blockIdx.x * blockDim.x + threadIdx.x;
    if (i * 4 >= E) return;
    int4 d4 = ((const int4*)(ei + E))[i];
    int r0 = atomicAdd(&g_count[d4.x], 1);
    int r1 = atomicAdd(&g_count[d4.y], 1);
    int r2 = atomicAdd(&g_count[d4.z], 1);
    int r3 = atomicAdd(&g_count[d4.w], 1);
    ((int4*)g_rank)[i] = make_int4(r0, r1, r2, r3);
}

// ---------------------------------------------------------------------------
// Single-kernel exclusive scan with software grid sync.
// 98 blocks x 1024 threads: all co-resident on 148 SMs -> spin-sync is safe.
// Release counter is monotone across graph replays; arrive counter is reset
// by block 0 before release, so every replay sees a clean state.
// ---------------------------------------------------------------------------
__global__ __launch_bounds__(1024) void scan_sync_kernel(int N, int E) {
    __shared__ int sm[1024];
    __shared__ int sp[128];
    __shared__ int s_off;
    int t = threadIdx.x, blk = blockIdx.x;
    int idx = blk * 1024 + t;

    int rel0 = 0;
    if (t == 0) rel0 = *((volatile int*)&g_release_ctr);

    int v = (idx < N) ? g_count[idx] : 0;
    sm[t] = v;
    __syncthreads();
    // block-level inclusive scan
    for (int off = 1; off < 1024; off <<= 1) {
        int u = (t >= off) ? sm[t - off] : 0;
        __syncthreads();
        sm[t] += u;
        __syncthreads();
    }
    if (t == 0) {
        g_part[blk] = sm[1023];
        __threadfence();
        atomicAdd(&g_arrive_ctr, 1);
    }

    if (blk == 0) {
        if (t == 0) {
            while (*((volatile int*)&g_arrive_ctr) < SCAN_BLKS) { }
        }
        __syncthreads();
        int pv = 0;
        if (t < SCAN_BLKS) pv = g_part[t];
        if (t < 128) sp[t] = (t < SCAN_BLKS) ? pv : 0;
        __syncthreads();
        for (int off = 1; off < 128; off <<= 1) {
            int u = (t >= off && t < 128) ? sp[t - off] : 0;
            __syncthreads();
            if (t < 128) sp[t] += u;
            __syncthreads();
        }
        if (t < SCAN_BLKS) g_part_off[t] = sp[t] - pv;   // exclusive
        __syncthreads();
        if (t == 0) {
            g_off[N] = E;
            __threadfence();
            g_arrive_ctr = 0;        // reset for next replay
            __threadfence();
            atomicAdd(&g_release_ctr, 1);
        }
    }

    if (t == 0) {
        while (*((volatile int*)&g_release_ctr) == rel0) { }
        s_off = g_part_off[blk];
    }
    __syncthreads();
    if (idx < N) {
        int ex = sm[t] - v + s_off;
        g_off[idx] = ex;
    }
}

// ---------------------------------------------------------------------------
// Place edges into CSR slots — ATOMIC-FREE: p = g_off[dst] + rank[e].
// 4 edges per thread. record = {src, k0, k1, k2}
// (launch index 3 -> this is the kernel ncu profiles)
// ---------------------------------------------------------------------------
__global__ void place_kernel(const int* __restrict__ ei,
                             const float* __restrict__ K, int E) {
    int i = blockIdx.x * blockDim.x + threadIdx.x;
    if (i * 4 >= E) return;
    int4   s4 = ((const int4*)ei)[i];
    int4   d4 = ((const int4*)(ei + E))[i];
    int4   r4 = ((const int4*)g_rank)[i];
    float4 k0 = ((const float4*)K)[i];
    float4 k1 = ((const float4*)(K + E))[i];
    float4 k2 = ((const float4*)(K + 2 * E))[i];
    int p0 = __ldg(&g_off[d4.x]) + r4.x;
    int p1 = __ldg(&g_off[d4.y]) + r4.y;
    int p2 = __ldg(&g_off[d4.z]) + r4.z;
    int p3 = __ldg(&g_off[d4.w]) + r4.w;
    g_edges[p0] = make_float4(__int_as_float(s4.x), k0.x, k1.x, k2.x);
    g_edges[p1] = make_float4(__int_as_float(s4.y), k0.y, k1.y, k2.y);
    g_edges[p2] = make_float4(__int_as_float(s4.z), k0.z, k1.z, k2.z);
    g_edges[p3] = make_float4(__int_as_float(s4.w), k0.w, k1.w, k2.w);
}

// ---------------------------------------------------------------------------
// conv1 gather: FOUR threads per node (4x memory-level parallelism).
// lanes 4q..4q+3 of a warp cooperate on one node; shfl_xor quad-reduce.
// ---------------------------------------------------------------------------
__global__ __launch_bounds__(256) void conv1_gather(int N) {
    int T = blockIdx.x * blockDim.x + threadIdx.x;
    int n = T >> 2;
    int sub = T & 3;
    int b = 0, en = 0;
    if (n < N) { b = g_off[n]; en = g_off[n + 1]; }
    float a[9];
#pragma unroll
    for (int c = 0; c < 9; c++) a[c] = 0.f;
    for (int i = b + sub; i < en; i += 4) {
        float4 r = g_edges[i];
        int s = __float_as_int(r.x);
        float4 xv = ((const float4*)g_xl)[s];
        a[0] += r.y * xv.x; a[1] += r.z * xv.x; a[2] += r.w * xv.x;
        a[3] += r.y * xv.y; a[4] += r.z * xv.y; a[5] += r.w * xv.y;
        a[6] += r.y * xv.z; a[7] += r.z * xv.z; a[8] += r.w * xv.z;
    }
    // quad reduction (lanes differing in bits 0-1 share a node)
#pragma unroll
    for (int c = 0; c < 9; c++) {
        a[c] += __shfl_xor_sync(0xFFFFFFFFu, a[c], 1);
        a[c] += __shfl_xor_sync(0xFFFFFFFFu, a[c], 2);
    }
    if (sub == 0 && n < N) {
        float4* row = (float4*)(g_h1 + n * 16);
        row[0] = make_float4(a[0], a[1], a[2], a[3]);
        row[1] = make_float4(a[4], a[5], a[6], a[7]);
        row[2] = make_float4(a[8], 0.f, 0.f, 0.f);
    }
}

// ---------------------------------------------------------------------------
// conv2 gather: FOUR threads per node, 27 accumulators, quad-reduce.
// ---------------------------------------------------------------------------
__global__ __launch_bounds__(256) void conv2_gather(int N) {
    int T = blockIdx.x * blockDim.x + threadIdx.x;
    int n = T >> 2;
    int sub = T & 3;
    int b = 0, en = 0;
    if (n < N) { b = g_off[n]; en = g_off[n + 1]; }
    float acc[27];
#pragma unroll
    for (int c = 0; c < 27; c++) acc[c] = 0.f;
    for (int i = b + sub; i < en; i += 4) {
        float4 r = g_edges[i];
        int s = __float_as_int(r.x);
        const float4* h1r = (const float4*)(g_h1 + s * 16);
        float4 A = h1r[0], B = h1r[1], C = h1r[2];
        float a[9] = {A.x, A.y, A.z, A.w, B.x, B.y, B.z, B.w, C.x};
#pragma unroll
        for (int c = 0; c < 9; c++) {
            acc[3 * c + 0] += r.y * a[c];
            acc[3 * c + 1] += r.z * a[c];
            acc[3 * c + 2] += r.w * a[c];
        }
    }
#pragma unroll
    for (int c = 0; c < 27; c++) {
        acc[c] += __shfl_xor_sync(0xFFFFFFFFu, acc[c], 1);
        acc[c] += __shfl_xor_sync(0xFFFFFFFFu, acc[c], 2);
    }
    if (sub == 0 && n < N) {
        float* row = g_h2 + n * 28;
#pragma unroll
        for (int q = 0; q < 6; q++)
            ((float4*)row)[q] = make_float4(acc[4 * q], acc[4 * q + 1],
                                            acc[4 * q + 2], acc[4 * q + 3]);
        ((float4*)row)[6] = make_float4(acc[24], acc[25], acc[26], 0.f);
    }
}

// ---------------------------------------------------------------------------
// MLP: packed f32x2 FFMA + LDS.128.
// feats[39] = [xl(3) | h1(9) | h2(27)];  relu(feats@W1+b1)@W2+b2 -> out[64]
// ---------------------------------------------------------------------------
__global__ __launch_bounds__(256) void mlp_kernel(
    const float* __restrict__ W1, const float* __restrict__ b1,
    const float* __restrict__ W2, const float* __restrict__ b2,
    float* __restrict__ out, int N) {
    __shared__ float sh_feats[39 * NT];        // [j][n]
    __shared__ float sh_hmid[HID * 36];        // [h][n], stride 36

    int t = threadIdx.x;
    int node0 = blockIdx.x * NT;

    // --- load feats (transposed) ---
    {
        int n = t & (NT - 1);
        int node = node0 + n;
        bool valid = node < N;
        for (int j = t >> 5; j < 39; j += 8) {
            float v = 0.f;
            if (valid) {
                if (j < 3)       v = g_xl[node * 4 + j];
                else if (j < 12) v = g_h1[node * 16 + (j - 3)];
                else             v = g_h2[node * 28 + (j - 12)];
            }
            sh_feats[j * NT + n] = v;
        }
    }
    __syncthreads();

    // --- layer 1: hidden unit t for 32 nodes, packed f32x2 accumulators ---
    unsigned long long acc2[NT / 2];
#pragma unroll
    for (int q = 0; q < NT / 2; q++) acc2[q] = 0ULL;

    for (int j = 0; j < 39; j++) {
        float w = __ldg(W1 + j * HID + t);
        unsigned long long wp; PACK_DUP(wp, w);
        const float4* f4 = (const float4*)(sh_feats + j * NT);
#pragma unroll
        for (int q = 0; q < NT / 4; q++) {
            float4 f = f4[q];               // broadcast LDS.128
            unsigned long long flo, fhi;
            PACK2(flo, f.x, f.y);
            PACK2(fhi, f.z, f.w);
            FMA_F32X2(acc2[2 * q + 0], flo, wp);
            FMA_F32X2(acc2[2 * q + 1], fhi, wp);
        }
    }
    {
        float bb = __ldg(b1 + t);
        float* hr = sh_hmid + t * 36;
#pragma unroll
        for (int q = 0; q < NT / 2; q++) {
            float lo, hi; UNPACK2(lo, hi, acc2[q]);
            hr[2 * q + 0] = fmaxf(lo + bb, 0.f);
            hr[2 * q + 1] = fmaxf(hi + bb, 0.f);
        }
    }
    __syncthreads();

    // --- layer 2: 4 nodes x 2 outputs per thread ---
    int ng = t & 7;
    int og = t >> 3;
    int nb = 4 * ng;
    int o0 = 2 * og;
    unsigned long long p0o0 = 0, p0o1 = 0, p1o0 = 0, p1o1 = 0;
#pragma unroll 4
    for (int h = 0; h < HID; h++) {
        float4 hm = *(const float4*)(sh_hmid + h * 36 + nb);   // LDS.128
        unsigned long long hm01, hm23;
        PACK2(hm01, hm.x, hm.y);
        PACK2(hm23, hm.z, hm.w);
        float2 w = __ldg((const float2*)(W2 + h * OUT + o0));
        unsigned long long w0p, w1p;
        PACK_DUP(w0p, w.x);
        PACK_DUP(w1p, w.y);
        FMA_F32X2(p0o0, hm01, w0p);
        FMA_F32X2(p0o1, hm01, w1p);
        FMA_F32X2(p1o0, hm23, w0p);
        FMA_F32X2(p1o1, hm23, w1p);
    }
    float bo0 = __ldg(b2 + o0), bo1 = __ldg(b2 + o0 + 1);
    float n0o0, n1o0, n2o0, n3o0, n0o1, n1o1, n2o1, n3o1;
    UNPACK2(n0o0, n1o0, p0o0);
    UNPACK2(n0o1, n1o1, p0o1);
    UNPACK2(n2o0, n3o0, p1o0);
    UNPACK2(n2o1, n3o1, p1o1);
    int node = node0 + nb;
    if (node + 0 < N) *(float2*)(out + (node + 0) * OUT + o0) = make_float2(n0o0 + bo0, n0o1 + bo1);
    if (node + 1 < N) *(float2*)(out + (node + 1) * OUT + o0) = make_float2(n1o0 + bo0, n1o1 + bo1);
    if (node + 2 < N) *(float2*)(out + (node + 2) * OUT + o0) = make_float2(n2o0 + bo0, n2o1 + bo1);
    if (node + 3 < N) *(float2*)(out + (node + 3) * OUT + o0) = make_float2(n3o0 + bo0, n3o1 + bo1);
}

// ---------------------------------------------------------------------------
// Launch: xl_zero -> hist(rank) -> scan_sync -> place -> conv1 -> conv2 -> mlp
// Inputs (metadata order): x, gauges, kernel_vals, W1, b1, W2, b2, edge_index
// ---------------------------------------------------------------------------
extern "C" void kernel_launch(void* const* d_in, const int* in_sizes, int n_in,
                              void* d_out, int out_size) {
    const float* x      = (const float*)d_in[0];
    const float* gauges = (const float*)d_in[1];
    const float* kvals  = (const float*)d_in[2];
    const float* W1     = (const float*)d_in[3];
    const float* b1     = (const float*)d_in[4];
    const float* W2     = (const float*)d_in[5];
    const float* b2     = (const float*)d_in[6];
    const int*   ei     = (const int*)d_in[7];   // int32 (JAX x64 disabled)
    float* out = (float*)d_out;

    int N = in_sizes[0] / 3;       // 100000
    int E = in_sizes[2] / 3;       // 6400000

    xl_zero_kernel<<<(N + 255) / 256, 256>>>(x, gauges, N);
    hist_kernel<<<(E / 4 + 255) / 256, 256>>>(ei, E);
    scan_sync_kernel<<<SCAN_BLKS, 1024>>>(N, E);
    place_kernel<<<(E / 4 + 255) / 256, 256>>>(ei, kvals, E);   // launch idx 3 -> profiled
    conv1_gather<<<(4 * N + 255) / 256, 256>>>(N);
    conv2_gather<<<(4 * N + 255) / 256, 256>>>(N);
    mlp_kernel<<<(N + NT - 1) / NT, 256>>>(W1, b1, W2, b2, out, N);
}

// round 9
// speedup vs baseline: 1.0519x; 1.0519x over previous
#include <cuda_runtime.h>
#include <cuda_bf16.h>

// Problem constants (fixed shapes for this problem instance)
#define NMAX 100000
#define EMAX 6400000
#define HID  256
#define OUT  64
#define NT   32      // nodes per MLP tile
#define SCAN_BLKS ((NMAX + 1023) / 1024)   // 98

// Scratch (device globals: no allocation allowed in kernel_launch)
__device__ float g_xl[NMAX * 4];    // stride 4, 16B rows
__device__ float g_h1[NMAX * 16];   // stride 16, 64B rows
__device__ float g_h2[NMAX * 28];   // stride 28
__device__ int    g_count[NMAX];           // static-init zero; re-zeroed by scan each replay
__device__ int    g_off[NMAX + 1];
__device__ int    g_cursor[NMAX];
__device__ int    g_part[SCAN_BLKS];       // per-block sums
__device__ int    g_part_off[SCAN_BLKS];   // exclusive offsets of block sums
__device__ int    g_arrive_ctr;            // grid-sync arrive counter (reset each use)
__device__ int    g_release_ctr;           // grid-sync release epoch (monotone)
__device__ float4 g_edges[EMAX];    // {src(as int bits), k0, k1, k2} sorted by dst

// packed f32x2 helpers (bit-identical to scalar fp32 math)
#define FMA_F32X2(acc, a, b) \
    asm("fma.rn.f32x2 %0, %1, %2, %0;" : "+l"(acc) : "l"(a), "l"(b))
#define PACK_DUP(out, s) \
    asm("mov.b64 %0, {%1, %1};" : "=l"(out) : "f"(s))
#define PACK2(out, lo, hi) \
    asm("mov.b64 %0, {%1, %2};" : "=l"(out) : "f"(lo), "f"(hi))
#define UNPACK2(lo, hi, in) \
    asm("mov.b64 {%0, %1}, %2;" : "=f"(lo), "=f"(hi) : "l"(in))

// ---------------------------------------------------------------------------
// Fused xl + histogram. Grid covers E/4 quads; first N threads also compute
// the gauge projection. g_count starts zero (static init / re-zeroed by scan).
// ---------------------------------------------------------------------------
__global__ void xl_hist_kernel(const float* __restrict__ x,
                               const float* __restrict__ g,
                               const int* __restrict__ ei, int N, int E) {
    int i = blockIdx.x * blockDim.x + threadIdx.x;

    if (i < N) {
        float x0 = x[i * 3 + 0], x1 = x[i * 3 + 1], x2 = x[i * 3 + 2];
        const float* G = g + i * 9;
        float o0 = x0 * G[0] + x1 * G[3] + x2 * G[6];
        float o1 = x0 * G[1] + x1 * G[4] + x2 * G[7];
        float o2 = x0 * G[2] + x1 * G[5] + x2 * G[8];
        ((float4*)g_xl)[i] = make_float4(o0, o1, o2, 0.f);
    }

    if (i * 4 < E) {
        int4 d4 = ((const int4*)(ei + E))[i];
        atomicAdd(&g_count[d4.x], 1);
        atomicAdd(&g_count[d4.y], 1);
        atomicAdd(&g_count[d4.z], 1);
        atomicAdd(&g_count[d4.w], 1);
    }
}

// ---------------------------------------------------------------------------
// Single-kernel exclusive scan with software grid sync.
// Also re-zeroes g_count after reading it (ready for next graph replay).
// 98 blocks x 1024 threads co-resident on 148 SMs -> spin-sync is safe.
// ---------------------------------------------------------------------------
__global__ __launch_bounds__(1024) void scan_sync_kernel(int N, int E) {
    __shared__ int sm[1024];
    __shared__ int sp[128];
    __shared__ int s_off;
    int t = threadIdx.x, blk = blockIdx.x;
    int idx = blk * 1024 + t;

    int rel0 = 0;
    if (t == 0) rel0 = *((volatile int*)&g_release_ctr);

    int v = 0;
    if (idx < N) {
        v = g_count[idx];
        g_count[idx] = 0;          // re-zero for next replay
    }
    sm[t] = v;
    __syncthreads();
    // block-level inclusive scan
    for (int off = 1; off < 1024; off <<= 1) {
        int u = (t >= off) ? sm[t - off] : 0;
        __syncthreads();
        sm[t] += u;
        __syncthreads();
    }
    if (t == 0) {
        g_part[blk] = sm[1023];
        __threadfence();
        atomicAdd(&g_arrive_ctr, 1);
    }

    if (blk == 0) {
        if (t == 0) {
            while (*((volatile int*)&g_arrive_ctr) < SCAN_BLKS) { }
        }
        __syncthreads();
        int pv = 0;
        if (t < SCAN_BLKS) pv = g_part[t];
        if (t < 128) sp[t] = (t < SCAN_BLKS) ? pv : 0;
        __syncthreads();
        for (int off = 1; off < 128; off <<= 1) {
            int u = (t >= off && t < 128) ? sp[t - off] : 0;
            __syncthreads();
            if (t < 128) sp[t] += u;
            __syncthreads();
        }
        if (t < SCAN_BLKS) g_part_off[t] = sp[t] - pv;   // exclusive
        __syncthreads();
        if (t == 0) {
            g_off[N] = E;
            __threadfence();
            g_arrive_ctr = 0;        // reset for next replay
            __threadfence();
            atomicAdd(&g_release_ctr, 1);
        }
    }

    if (t == 0) {
        while (*((volatile int*)&g_release_ctr) == rel0) { }
        s_off = g_part_off[blk];
    }
    __syncthreads();
    if (idx < N) {
        int ex = sm[t] - v + s_off;
        g_off[idx]    = ex;
        g_cursor[idx] = ex;
    }
}

// ---------------------------------------------------------------------------
// Place edges into CSR slots, 4 edges per thread (atomic cursor — the
// scattered 16B stores are the wall, not the atomics). record = {src,k0,k1,k2}
// ---------------------------------------------------------------------------
__global__ void place_kernel(const int* __restrict__ ei,
                             const float* __restrict__ K, int E) {
    int i = blockIdx.x * blockDim.x + threadIdx.x;
    if (i * 4 >= E) return;
    int4   s4 = ((const int4*)ei)[i];
    int4   d4 = ((const int4*)(ei + E))[i];
    float4 k0 = ((const float4*)K)[i];
    float4 k1 = ((const float4*)(K + E))[i];
    float4 k2 = ((const float4*)(K + 2 * E))[i];
    int p0 = atomicAdd(&g_cursor[d4.x], 1);
    int p1 = atomicAdd(&g_cursor[d4.y], 1);
    int p2 = atomicAdd(&g_cursor[d4.z], 1);
    int p3 = atomicAdd(&g_cursor[d4.w], 1);
    g_edges[p0] = make_float4(__int_as_float(s4.x), k0.x, k1.x, k2.x);
    g_edges[p1] = make_float4(__int_as_float(s4.y), k0.y, k1.y, k2.y);
    g_edges[p2] = make_float4(__int_as_float(s4.z), k0.z, k1.z, k2.z);
    g_edges[p3] = make_float4(__int_as_float(s4.w), k0.w, k1.w, k2.w);
}

// ---------------------------------------------------------------------------
// conv1 gather: FOUR threads per node; shfl_xor quad-reduce.
// (launch index 3 -> this is the kernel ncu profiles this round)
// ---------------------------------------------------------------------------
__global__ __launch_bounds__(256) void conv1_gather(int N) {
    int T = blockIdx.x * blockDim.x + threadIdx.x;
    int n = T >> 2;
    int sub = T & 3;
    int b = 0, en = 0;
    if (n < N) { b = g_off[n]; en = g_off[n + 1]; }
    float a[9];
#pragma unroll
    for (int c = 0; c < 9; c++) a[c] = 0.f;
    for (int i = b + sub; i < en; i += 4) {
        float4 r = g_edges[i];
        int s = __float_as_int(r.x);
        float4 xv = ((const float4*)g_xl)[s];
        a[0] += r.y * xv.x; a[1] += r.z * xv.x; a[2] += r.w * xv.x;
        a[3] += r.y * xv.y; a[4] += r.z * xv.y; a[5] += r.w * xv.y;
        a[6] += r.y * xv.z; a[7] += r.z * xv.z; a[8] += r.w * xv.z;
    }
#pragma unroll
    for (int c = 0; c < 9; c++) {
        a[c] += __shfl_xor_sync(0xFFFFFFFFu, a[c], 1);
        a[c] += __shfl_xor_sync(0xFFFFFFFFu, a[c], 2);
    }
    if (sub == 0 && n < N) {
        float4* row = (float4*)(g_h1 + n * 16);
        row[0] = make_float4(a[0], a[1], a[2], a[3]);
        row[1] = make_float4(a[4], a[5], a[6], a[7]);
        row[2] = make_float4(a[8], 0.f, 0.f, 0.f);
    }
}

// ---------------------------------------------------------------------------
// conv2 gather: FOUR threads per node, 27 accumulators, quad-reduce.
// ---------------------------------------------------------------------------
__global__ __launch_bounds__(256) void conv2_gather(int N) {
    int T = blockIdx.x * blockDim.x + threadIdx.x;
    int n = T >> 2;
    int sub = T & 3;
    int b = 0, en = 0;
    if (n < N) { b = g_off[n]; en = g_off[n + 1]; }
    float acc[27];
#pragma unroll
    for (int c = 0; c < 27; c++) acc[c] = 0.f;
    for (int i = b + sub; i < en; i += 4) {
        float4 r = g_edges[i];
        int s = __float_as_int(r.x);
        const float4* h1r = (const float4*)(g_h1 + s * 16);
        float4 A = h1r[0], B = h1r[1], C = h1r[2];
        float a[9] = {A.x, A.y, A.z, A.w, B.x, B.y, B.z, B.w, C.x};
#pragma unroll
        for (int c = 0; c < 9; c++) {
            acc[3 * c + 0] += r.y * a[c];
            acc[3 * c + 1] += r.z * a[c];
            acc[3 * c + 2] += r.w * a[c];
        }
    }
#pragma unroll
    for (int c = 0; c < 27; c++) {
        acc[c] += __shfl_xor_sync(0xFFFFFFFFu, acc[c], 1);
        acc[c] += __shfl_xor_sync(0xFFFFFFFFu, acc[c], 2);
    }
    if (sub == 0 && n < N) {
        float* row = g_h2 + n * 28;
#pragma unroll
        for (int q = 0; q < 6; q++)
            ((float4*)row)[q] = make_float4(acc[4 * q], acc[4 * q + 1],
                                            acc[4 * q + 2], acc[4 * q + 3]);
        ((float4*)row)[6] = make_float4(acc[24], acc[25], acc[26], 0.f);
    }
}

// ---------------------------------------------------------------------------
// MLP: packed f32x2 FFMA + LDS.128.
// feats[39] = [xl(3) | h1(9) | h2(27)];  relu(feats@W1+b1)@W2+b2 -> out[64]
// ---------------------------------------------------------------------------
__global__ __launch_bounds__(256) void mlp_kernel(
    const float* __restrict__ W1, const float* __restrict__ b1,
    const float* __restrict__ W2, const float* __restrict__ b2,
    float* __restrict__ out, int N) {
    __shared__ float sh_feats[39 * NT];        // [j][n]
    __shared__ float sh_hmid[HID * 36];        // [h][n], stride 36

    int t = threadIdx.x;
    int node0 = blockIdx.x * NT;

    // --- load feats (transposed) ---
    {
        int n = t & (NT - 1);
        int node = node0 + n;
        bool valid = node < N;
        for (int j = t >> 5; j < 39; j += 8) {
            float v = 0.f;
            if (valid) {
                if (j < 3)       v = g_xl[node * 4 + j];
                else if (j < 12) v = g_h1[node * 16 + (j - 3)];
                else             v = g_h2[node * 28 + (j - 12)];
            }
            sh_feats[j * NT + n] = v;
        }
    }
    __syncthreads();

    // --- layer 1: hidden unit t for 32 nodes, packed f32x2 accumulators ---
    unsigned long long acc2[NT / 2];
#pragma unroll
    for (int q = 0; q < NT / 2; q++) acc2[q] = 0ULL;

    for (int j = 0; j < 39; j++) {
        float w = __ldg(W1 + j * HID + t);
        unsigned long long wp; PACK_DUP(wp, w);
        const float4* f4 = (const float4*)(sh_feats + j * NT);
#pragma unroll
        for (int q = 0; q < NT / 4; q++) {
            float4 f = f4[q];               // broadcast LDS.128
            unsigned long long flo, fhi;
            PACK2(flo, f.x, f.y);
            PACK2(fhi, f.z, f.w);
            FMA_F32X2(acc2[2 * q + 0], flo, wp);
            FMA_F32X2(acc2[2 * q + 1], fhi, wp);
        }
    }
    {
        float bb = __ldg(b1 + t);
        float* hr = sh_hmid + t * 36;
#pragma unroll
        for (int q = 0; q < NT / 2; q++) {
            float lo, hi; UNPACK2(lo, hi, acc2[q]);
            hr[2 * q + 0] = fmaxf(lo + bb, 0.f);
            hr[2 * q + 1] = fmaxf(hi + bb, 0.f);
        }
    }
    __syncthreads();

    // --- layer 2: 4 nodes x 2 outputs per thread ---
    int ng = t & 7;
    int og = t >> 3;
    int nb = 4 * ng;
    int o0 = 2 * og;
    unsigned long long p0o0 = 0, p0o1 = 0, p1o0 = 0, p1o1 = 0;
#pragma unroll 4
    for (int h = 0; h < HID; h++) {
        float4 hm = *(const float4*)(sh_hmid + h * 36 + nb);   // LDS.128
        unsigned long long hm01, hm23;
        PACK2(hm01, hm.x, hm.y);
        PACK2(hm23, hm.z, hm.w);
        float2 w = __ldg((const float2*)(W2 + h * OUT + o0));
        unsigned long long w0p, w1p;
        PACK_DUP(w0p, w.x);
        PACK_DUP(w1p, w.y);
        FMA_F32X2(p0o0, hm01, w0p);
        FMA_F32X2(p0o1, hm01, w1p);
        FMA_F32X2(p1o0, hm23, w0p);
        FMA_F32X2(p1o1, hm23, w1p);
    }
    float bo0 = __ldg(b2 + o0), bo1 = __ldg(b2 + o0 + 1);
    float n0o0, n1o0, n2o0, n3o0, n0o1, n1o1, n2o1, n3o1;
    UNPACK2(n0o0, n1o0, p0o0);
    UNPACK2(n0o1, n1o1, p0o1);
    UNPACK2(n2o0, n3o0, p1o0);
    UNPACK2(n2o1, n3o1, p1o1);
    int node = node0 + nb;
    if (node + 0 < N) *(float2*)(out + (node + 0) * OUT + o0) = make_float2(n0o0 + bo0, n0o1 + bo1);
    if (node + 1 < N) *(float2*)(out + (node + 1) * OUT + o0) = make_float2(n1o0 + bo0, n1o1 + bo1);
    if (node + 2 < N) *(float2*)(out + (node + 2) * OUT + o0) = make_float2(n2o0 + bo0, n2o1 + bo1);
    if (node + 3 < N) *(float2*)(out + (node + 3) * OUT + o0) = make_float2(n3o0 + bo0, n3o1 + bo1);
}

// ---------------------------------------------------------------------------
// Launch: xl_hist -> scan_sync -> place -> conv1 -> conv2 -> mlp
// Inputs (metadata order): x, gauges, kernel_vals, W1, b1, W2, b2, edge_index
// ---------------------------------------------------------------------------
extern "C" void kernel_launch(void* const* d_in, const int* in_sizes, int n_in,
                              void* d_out, int out_size) {
    const float* x      = (const float*)d_in[0];
    const float* gauges = (const float*)d_in[1];
    const float* kvals  = (const float*)d_in[2];
    const float* W1     = (const float*)d_in[3];
    const float* b1     = (const float*)d_in[4];
    const float* W2     = (const float*)d_in[5];
    const float* b2     = (const float*)d_in[6];
    const int*   ei     = (const int*)d_in[7];   // int32 (JAX x64 disabled)
    float* out = (float*)d_out;

    int N = in_sizes[0] / 3;       // 100000
    int E = in_sizes[2] / 3;       // 6400000

    xl_hist_kernel<<<(E / 4 + 255) / 256, 256>>>(x, gauges, ei, N, E);
    scan_sync_kernel<<<SCAN_BLKS, 1024>>>(N, E);
    place_kernel<<<(E / 4 + 255) / 256, 256>>>(ei, kvals, E);
    conv1_gather<<<(4 * N + 255) / 256, 256>>>(N);   // launch idx 3 -> profiled
    conv2_gather<<<(4 * N + 255) / 256, 256>>>(N);
    mlp_kernel<<<(N + NT - 1) / NT, 256>>>(W1, b1, W2, b2, out, N);
}

// round 10
// speedup vs baseline: 1.0916x; 1.0377x over previous
#include <cuda_runtime.h>
#include <cuda_bf16.h>

// Problem constants (fixed shapes for this problem instance)
#define NMAX 100000
#define EMAX 6400000
#define HID  256
#define OUT  64
#define NT   32      // nodes per MLP tile
#define HSTR 34      // sh_hmid row stride (floats); 34*4=136B, 8B-aligned pairs
#define SCAN_BLKS ((NMAX + 1023) / 1024)   // 98

// Scratch (device globals: no allocation allowed in kernel_launch)
__device__ float g_xl[NMAX * 4];    // stride 4, 16B rows
__device__ float g_h1[NMAX * 16];   // stride 16, 64B rows
__device__ float g_h2[NMAX * 28];   // stride 28
__device__ int    g_count[NMAX];           // static-init zero; re-zeroed by scan each replay
__device__ int    g_off[NMAX + 1];
__device__ int    g_cursor[NMAX];
__device__ int    g_part[SCAN_BLKS];       // per-block sums
__device__ int    g_part_off[SCAN_BLKS];   // exclusive offsets of block sums
__device__ int    g_arrive_ctr;            // grid-sync arrive counter (reset each use)
__device__ int    g_release_ctr;           // grid-sync release epoch (monotone)
__device__ float4 g_edges[EMAX];    // {src(as int bits), k0, k1, k2} sorted by dst

// packed f32x2 helpers (bit-identical to scalar fp32 math)
#define FMA_F32X2(acc, a, b) \
    asm("fma.rn.f32x2 %0, %1, %2, %0;" : "+l"(acc) : "l"(a), "l"(b))
#define PACK_DUP(out, s) \
    asm("mov.b64 %0, {%1, %1};" : "=l"(out) : "f"(s))
#define PACK2(out, lo, hi) \
    asm("mov.b64 %0, {%1, %2};" : "=l"(out) : "f"(lo), "f"(hi))
#define UNPACK2(lo, hi, in) \
    asm("mov.b64 {%0, %1}, %2;" : "=f"(lo), "=f"(hi) : "l"(in))

// ---------------------------------------------------------------------------
// Fused xl + histogram. Grid covers E/4 quads; first N threads also compute
// the gauge projection. g_count starts zero (static init / re-zeroed by scan).
// ---------------------------------------------------------------------------
__global__ void xl_hist_kernel(const float* __restrict__ x,
                               const float* __restrict__ g,
                               const int* __restrict__ ei, int N, int E) {
    int i = blockIdx.x * blockDim.x + threadIdx.x;

    if (i < N) {
        float x0 = x[i * 3 + 0], x1 = x[i * 3 + 1], x2 = x[i * 3 + 2];
        const float* G = g + i * 9;
        float o0 = x0 * G[0] + x1 * G[3] + x2 * G[6];
        float o1 = x0 * G[1] + x1 * G[4] + x2 * G[7];
        float o2 = x0 * G[2] + x1 * G[5] + x2 * G[8];
        ((float4*)g_xl)[i] = make_float4(o0, o1, o2, 0.f);
    }

    if (i * 4 < E) {
        int4 d4 = ((const int4*)(ei + E))[i];
        atomicAdd(&g_count[d4.x], 1);
        atomicAdd(&g_count[d4.y], 1);
        atomicAdd(&g_count[d4.z], 1);
        atomicAdd(&g_count[d4.w], 1);
    }
}

// ---------------------------------------------------------------------------
// Single-kernel exclusive scan with software grid sync.
// Also re-zeroes g_count after reading it (ready for next graph replay).
// 98 blocks x 1024 threads co-resident on 148 SMs -> spin-sync is safe.
// ---------------------------------------------------------------------------
__global__ __launch_bounds__(1024) void scan_sync_kernel(int N, int E) {
    __shared__ int sm[1024];
    __shared__ int sp[128];
    __shared__ int s_off;
    int t = threadIdx.x, blk = blockIdx.x;
    int idx = blk * 1024 + t;

    int rel0 = 0;
    if (t == 0) rel0 = *((volatile int*)&g_release_ctr);

    int v = 0;
    if (idx < N) {
        v = g_count[idx];
        g_count[idx] = 0;          // re-zero for next replay
    }
    sm[t] = v;
    __syncthreads();
    // block-level inclusive scan
    for (int off = 1; off < 1024; off <<= 1) {
        int u = (t >= off) ? sm[t - off] : 0;
        __syncthreads();
        sm[t] += u;
        __syncthreads();
    }
    if (t == 0) {
        g_part[blk] = sm[1023];
        __threadfence();
        atomicAdd(&g_arrive_ctr, 1);
    }

    if (blk == 0) {
        if (t == 0) {
            while (*((volatile int*)&g_arrive_ctr) < SCAN_BLKS) { }
        }
        __syncthreads();
        int pv = 0;
        if (t < SCAN_BLKS) pv = g_part[t];
        if (t < 128) sp[t] = (t < SCAN_BLKS) ? pv : 0;
        __syncthreads();
        for (int off = 1; off < 128; off <<= 1) {
            int u = (t >= off && t < 128) ? sp[t - off] : 0;
            __syncthreads();
            if (t < 128) sp[t] += u;
            __syncthreads();
        }
        if (t < SCAN_BLKS) g_part_off[t] = sp[t] - pv;   // exclusive
        __syncthreads();
        if (t == 0) {
            g_off[N] = E;
            __threadfence();
            g_arrive_ctr = 0;        // reset for next replay
            __threadfence();
            atomicAdd(&g_release_ctr, 1);
        }
    }

    if (t == 0) {
        while (*((volatile int*)&g_release_ctr) == rel0) { }
        s_off = g_part_off[blk];
    }
    __syncthreads();
    if (idx < N) {
        int ex = sm[t] - v + s_off;
        g_off[idx]    = ex;
        g_cursor[idx] = ex;
    }
}

// ---------------------------------------------------------------------------
// Place edges into CSR slots, 4 edges per thread (atomic cursor — the
// scattered 16B stores are the wall, not the atomics). record = {src,k0,k1,k2}
// ---------------------------------------------------------------------------
__global__ void place_kernel(const int* __restrict__ ei,
                             const float* __restrict__ K, int E) {
    int i = blockIdx.x * blockDim.x + threadIdx.x;
    if (i * 4 >= E) return;
    int4   s4 = ((const int4*)ei)[i];
    int4   d4 = ((const int4*)(ei + E))[i];
    float4 k0 = ((const float4*)K)[i];
    float4 k1 = ((const float4*)(K + E))[i];
    float4 k2 = ((const float4*)(K + 2 * E))[i];
    int p0 = atomicAdd(&g_cursor[d4.x], 1);
    int p1 = atomicAdd(&g_cursor[d4.y], 1);
    int p2 = atomicAdd(&g_cursor[d4.z], 1);
    int p3 = atomicAdd(&g_cursor[d4.w], 1);
    g_edges[p0] = make_float4(__int_as_float(s4.x), k0.x, k1.x, k2.x);
    g_edges[p1] = make_float4(__int_as_float(s4.y), k0.y, k1.y, k2.y);
    g_edges[p2] = make_float4(__int_as_float(s4.z), k0.z, k1.z, k2.z);
    g_edges[p3] = make_float4(__int_as_float(s4.w), k0.w, k1.w, k2.w);
}

// ---------------------------------------------------------------------------
// conv1 gather: FOUR threads per node; shfl_xor quad-reduce.
// ---------------------------------------------------------------------------
__global__ __launch_bounds__(256) void conv1_gather(int N) {
    int T = blockIdx.x * blockDim.x + threadIdx.x;
    int n = T >> 2;
    int sub = T & 3;
    int b = 0, en = 0;
    if (n < N) { b = g_off[n]; en = g_off[n + 1]; }
    float a[9];
#pragma unroll
    for (int c = 0; c < 9; c++) a[c] = 0.f;
    for (int i = b + sub; i < en; i += 4) {
        float4 r = g_edges[i];
        int s = __float_as_int(r.x);
        float4 xv = ((const float4*)g_xl)[s];
        a[0] += r.y * xv.x; a[1] += r.z * xv.x; a[2] += r.w * xv.x;
        a[3] += r.y * xv.y; a[4] += r.z * xv.y; a[5] += r.w * xv.y;
        a[6] += r.y * xv.z; a[7] += r.z * xv.z; a[8] += r.w * xv.z;
    }
#pragma unroll
    for (int c = 0; c < 9; c++) {
        a[c] += __shfl_xor_sync(0xFFFFFFFFu, a[c], 1);
        a[c] += __shfl_xor_sync(0xFFFFFFFFu, a[c], 2);
    }
    if (sub == 0 && n < N) {
        float4* row = (float4*)(g_h1 + n * 16);
        row[0] = make_float4(a[0], a[1], a[2], a[3]);
        row[1] = make_float4(a[4], a[5], a[6], a[7]);
        row[2] = make_float4(a[8], 0.f, 0.f, 0.f);
    }
}

// ---------------------------------------------------------------------------
// conv2 gather: FOUR threads per node, 27 accumulators, quad-reduce.
// ---------------------------------------------------------------------------
__global__ __launch_bounds__(256) void conv2_gather(int N) {
    int T = blockIdx.x * blockDim.x + threadIdx.x;
    int n = T >> 2;
    int sub = T & 3;
    int b = 0, en = 0;
    if (n < N) { b = g_off[n]; en = g_off[n + 1]; }
    float acc[27];
#pragma unroll
    for (int c = 0; c < 27; c++) acc[c] = 0.f;
    for (int i = b + sub; i < en; i += 4) {
        float4 r = g_edges[i];
        int s = __float_as_int(r.x);
        const float4* h1r = (const float4*)(g_h1 + s * 16);
        float4 A = h1r[0], B = h1r[1], C = h1r[2];
        float a[9] = {A.x, A.y, A.z, A.w, B.x, B.y, B.z, B.w, C.x};
#pragma unroll
        for (int c = 0; c < 9; c++) {
            acc[3 * c + 0] += r.y * a[c];
            acc[3 * c + 1] += r.z * a[c];
            acc[3 * c + 2] += r.w * a[c];
        }
    }
#pragma unroll
    for (int c = 0; c < 27; c++) {
        acc[c] += __shfl_xor_sync(0xFFFFFFFFu, acc[c], 1);
        acc[c] += __shfl_xor_sync(0xFFFFFFFFu, acc[c], 2);
    }
    if (sub == 0 && n < N) {
        float* row = g_h2 + n * 28;
#pragma unroll
        for (int q = 0; q < 6; q++)
            ((float4*)row)[q] = make_float4(acc[4 * q], acc[4 * q + 1],
                                            acc[4 * q + 2], acc[4 * q + 3]);
        ((float4*)row)[6] = make_float4(acc[24], acc[25], acc[26], 0.f);
    }
}

// ---------------------------------------------------------------------------
// MLP: packed f32x2 FFMA; layer-2 W2 staged through shared memory in 32-row
// chunks (kills the 65k-per-block LDG.64 wall; inner loop is LDS+FFMA2 only).
// feats[39] = [xl(3) | h1(9) | h2(27)];  relu(feats@W1+b1)@W2+b2 -> out[64]
// ---------------------------------------------------------------------------
__global__ __launch_bounds__(256) void mlp_kernel(
    const float* __restrict__ W1, const float* __restrict__ b1,
    const float* __restrict__ W2, const float* __restrict__ b2,
    float* __restrict__ out, int N) {
    __shared__ __align__(16) float  sh_feats[39 * NT];       // 4992 B
    __shared__ __align__(16) float  sh_hmid[HID * HSTR];     // 34816 B
    __shared__ __align__(16) float4 sh_w2[32 * OUT / 4];     // 8192 B  (one 32-row chunk)

    int t = threadIdx.x;
    int node0 = blockIdx.x * NT;

    // --- load feats (transposed) ---
    {
        int n = t & (NT - 1);
        int node = node0 + n;
        bool valid = node < N;
        for (int j = t >> 5; j < 39; j += 8) {
            float v = 0.f;
            if (valid) {
                if (j < 3)       v = g_xl[node * 4 + j];
                else if (j < 12) v = g_h1[node * 16 + (j - 3)];
                else             v = g_h2[node * 28 + (j - 12)];
            }
            sh_feats[j * NT + n] = v;
        }
    }
    __syncthreads();

    // --- layer 1: hidden unit t for 32 nodes, packed f32x2 accumulators ---
    unsigned long long acc2[NT / 2];
#pragma unroll
    for (int q = 0; q < NT / 2; q++) acc2[q] = 0ULL;

    for (int j = 0; j < 39; j++) {
        float w = __ldg(W1 + j * HID + t);
        unsigned long long wp; PACK_DUP(wp, w);
        const float4* f4 = (const float4*)(sh_feats + j * NT);
#pragma unroll
        for (int q = 0; q < NT / 4; q++) {
            float4 f = f4[q];               // broadcast LDS.128
            unsigned long long flo, fhi;
            PACK2(flo, f.x, f.y);
            PACK2(fhi, f.z, f.w);
            FMA_F32X2(acc2[2 * q + 0], flo, wp);
            FMA_F32X2(acc2[2 * q + 1], fhi, wp);
        }
    }
    {
        float bb = __ldg(b1 + t);
        float* hr = sh_hmid + t * HSTR;
#pragma unroll
        for (int q = 0; q < NT / 2; q++) {
            float lo, hi; UNPACK2(lo, hi, acc2[q]);
            hr[2 * q + 0] = fmaxf(lo + bb, 0.f);
            hr[2 * q + 1] = fmaxf(hi + bb, 0.f);
        }
    }

    // --- layer 2: 4 nodes x 2 outputs per thread; W2 chunk-staged in smem ---
    int ng = t & 7;
    int og = t >> 3;
    int nb = 4 * ng;
    int o0 = 2 * og;
    unsigned long long p0o0 = 0, p0o1 = 0, p1o0 = 0, p1o1 = 0;
    const float* w2f = (const float*)sh_w2;

    for (int c = 0; c < HID / 32; c++) {
        __syncthreads();   // (also covers the hmid writes before chunk 0)
        // stage W2 rows [32c, 32c+32): 32*64 floats = 512 float4, coalesced
        const float4* src = (const float4*)(W2 + c * 32 * OUT);
        sh_w2[t]       = src[t];
        sh_w2[t + 256] = src[t + 256];
        __syncthreads();
#pragma unroll
        for (int hh = 0; hh < 32; hh++) {
            int h = c * 32 + hh;
            unsigned long long hm01 = *(const unsigned long long*)(sh_hmid + h * HSTR + nb);
            unsigned long long hm23 = *(const unsigned long long*)(sh_hmid + h * HSTR + nb + 2);
            float2 w = *(const float2*)(w2f + hh * OUT + o0);
            unsigned long long w0p, w1p;
            PACK_DUP(w0p, w.x);
            PACK_DUP(w1p, w.y);
            FMA_F32X2(p0o0, hm01, w0p);
            FMA_F32X2(p0o1, hm01, w1p);
            FMA_F32X2(p1o0, hm23, w0p);
            FMA_F32X2(p1o1, hm23, w1p);
        }
    }

    float bo0 = __ldg(b2 + o0), bo1 = __ldg(b2 + o0 + 1);
    float n0o0, n1o0, n2o0, n3o0, n0o1, n1o1, n2o1, n3o1;
    UNPACK2(n0o0, n1o0, p0o0);
    UNPACK2(n0o1, n1o1, p0o1);
    UNPACK2(n2o0, n3o0, p1o0);
    UNPACK2(n2o1, n3o1, p1o1);
    int node = node0 + nb;
    if (node + 0 < N) *(float2*)(out + (node + 0) * OUT + o0) = make_float2(n0o0 + bo0, n0o1 + bo1);
    if (node + 1 < N) *(float2*)(out + (node + 1) * OUT + o0) = make_float2(n1o0 + bo0, n1o1 + bo1);
    if (node + 2 < N) *(float2*)(out + (node + 2) * OUT + o0) = make_float2(n2o0 + bo0, n2o1 + bo1);
    if (node + 3 < N) *(float2*)(out + (node + 3) * OUT + o0) = make_float2(n3o0 + bo0, n3o1 + bo1);
}

// ---------------------------------------------------------------------------
// Launch: xl_hist -> scan_sync -> place -> conv1 -> conv2 -> mlp
// Inputs (metadata order): x, gauges, kernel_vals, W1, b1, W2, b2, edge_index
// ---------------------------------------------------------------------------
extern "C" void kernel_launch(void* const* d_in, const int* in_sizes, int n_in,
                              void* d_out, int out_size) {
    const float* x      = (const float*)d_in[0];
    const float* gauges = (const float*)d_in[1];
    const float* kvals  = (const float*)d_in[2];
    const float* W1     = (const float*)d_in[3];
    const float* b1     = (const float*)d_in[4];
    const float* W2     = (const float*)d_in[5];
    const float* b2     = (const float*)d_in[6];
    const int*   ei     = (const int*)d_in[7];   // int32 (JAX x64 disabled)
    float* out = (float*)d_out;

    int N = in_sizes[0] / 3;       // 100000
    int E = in_sizes[2] / 3;       // 6400000

    xl_hist_kernel<<<(E / 4 + 255) / 256, 256>>>(x, gauges, ei, N, E);
    scan_sync_kernel<<<SCAN_BLKS, 1024>>>(N, E);
    place_kernel<<<(E / 4 + 255) / 256, 256>>>(ei, kvals, E);
    conv1_gather<<<(4 * N + 255) / 256, 256>>>(N);   // launch idx 3 -> profiled
    conv2_gather<<<(4 * N + 255) / 256, 256>>>(N);
    mlp_kernel<<<(N + NT - 1) / NT, 256>>>(W1, b1, W2, b2, out, N);
}